// round 6
// baseline (speedup 1.0000x reference)
#include <cuda_runtime.h>
#include <math.h>

#define E 128
#define C 64
#define TILE_N 64
#define THREADS 128
#define STRIDE 68          // k-major smem stride: 16B-aligned rows, 4-way store conflict on transpose only
#define EPSV 1e-5f
#define MAXB 1024

__device__ float g_part[MAXB][C + 8];   // per-block partials: [0..63] centroid sums, [64] mask sum
__device__ int   g_count = 0;

__global__ __launch_bounds__(THREADS, 3)
void cd_kernel(const float* __restrict__ node_repr,
               const float* __restrict__ maskp,
               const float* __restrict__ cent,
               float* __restrict__ out, int N) {
    extern __shared__ float smem[];
    float* sn     = smem;                  // [E][STRIDE], 64 node cols used
    float* sc     = sn + E * STRIDE;       // [E][STRIDE], 64 centroid cols used
    float* s_su   = sc + E * STRIDE;       // [64]
    float* s_ru   = s_su + TILE_N;         // [64]  1/(1-su)
    float* s_sv   = s_ru + TILE_N;         // [64]
    float* s_rv   = s_sv + C;              // [64]  1/(1-sv)
    float* s_mask = s_rv + C;              // [64]
    float* s_red  = s_mask + TILE_N;       // [64]
    __shared__ int   s_last;
    __shared__ float s_msum;

    const int tid = threadIdx.x;
    const int n0  = blockIdx.x * TILE_N;
    float* node_out = out + C;

    // ---- load phase: transpose gmem row-major -> smem k-major ----
    for (int idx = tid; idx < C * E; idx += THREADS) {
        int k = idx & (E - 1);
        int c = idx >> 7;
        sc[k * STRIDE + c] = cent[idx];
    }
    for (int idx = tid; idx < TILE_N * E; idx += THREADS) {
        int k = idx & (E - 1);
        int i = idx >> 7;
        int n = n0 + i;
        sn[k * STRIDE + i] = (n < N) ? node_repr[(size_t)n * E + k] : 0.0f;
    }
    if (tid < TILE_N) {
        int n = n0 + tid;
        s_mask[tid] = (n < N) ? maskp[n] : 0.0f;
        s_red[tid] = 0.0f;
    }
    __syncthreads();

    // ---- norms + reciprocals (few MUFU.RCP per block, not per element) ----
    if (tid < TILE_N) {
        float s = 0.f;
        #pragma unroll 8
        for (int k = 0; k < E; k++) { float v = sn[k * STRIDE + tid]; s = fmaf(v, v, s); }
        s_su[tid] = s;
        s_ru[tid] = __fdividef(1.0f, 1.0f - s);
    } else {
        int c = tid - TILE_N;
        float s = 0.f;
        #pragma unroll 8
        for (int k = 0; k < E; k++) { float v = sc[k * STRIDE + c]; s = fmaf(v, v, s); }
        s_sv[c] = s;
        s_rv[c] = __fdividef(1.0f, 1.0f - s);
    }
    __syncthreads();

    // ---- mainloop: 8 nodes x 4 centroids per thread ----
    const int tx = tid & 15;   // centroid group: 4*tx
    const int ty = tid >> 4;   // node group: 8*ty

    float acc[8][4];
    #pragma unroll
    for (int i = 0; i < 8; i++)
        #pragma unroll
        for (int j = 0; j < 4; j++) acc[i][j] = 0.f;

    const float* snp = sn + 8 * ty;
    const float* scp = sc + 4 * tx;

    #pragma unroll 4
    for (int k = 0; k < E; k++) {
        float4 cv  = *(const float4*)(scp + k * STRIDE);
        float4 na  = *(const float4*)(snp + k * STRIDE);
        float4 nb  = *(const float4*)(snp + k * STRIDE + 4);
        float nv[8] = {na.x, na.y, na.z, na.w, nb.x, nb.y, nb.z, nb.w};
        #pragma unroll
        for (int i = 0; i < 8; i++) {
            acc[i][0] = fmaf(nv[i], cv.x, acc[i][0]);
            acc[i][1] = fmaf(nv[i], cv.y, acc[i][1]);
            acc[i][2] = fmaf(nv[i], cv.z, acc[i][2]);
            acc[i][3] = fmaf(nv[i], cv.w, acc[i][3]);
        }
    }

    // ---- epilogue: series acosh, 1 MUFU.RSQ per element ----
    // acosh(1+y) = sqrt(2y)*(1 - y/12 + 3y^2/160 - 5y^3/896 + ...), y = 2*sq/denom = 2z
    float sv_r[4], rv_r[4];
    #pragma unroll
    for (int j = 0; j < 4; j++) { sv_r[j] = s_sv[4 * tx + j]; rv_r[j] = s_rv[4 * tx + j]; }

    float psum[4] = {0.f, 0.f, 0.f, 0.f};

    #pragma unroll
    for (int i = 0; i < 8; i++) {
        int ln = 8 * ty + i;
        int n  = n0 + ln;
        if (n < N) {
            float su = s_su[ln];
            float ru = s_ru[ln];
            float m  = s_mask[ln];
            float4 o;
            float* op = &o.x;
            #pragma unroll
            for (int j = 0; j < 4; j++) {
                float sq = fmaxf(fmaf(-2.f, acc[i][j], su + sv_r[j]), 0.f);
                float z  = fmaxf(sq * ru * rv_r[j], 0.5f * EPSV);   // z = sq/denom, y = 2z >= EPS
                float r  = rsqrtf(z);
                float sz = z * r;                                    // sqrt(z)
                float y  = 2.f * z;
                float poly = fmaf(y, fmaf(y, fmaf(y, -0.0055803572f, 0.01875f), -0.083333336f), 1.0f);
                float d  = 2.f * sz * poly * m;                      // sqrt(2y)*poly = 2*sqrt(z)*poly
                op[j] = d;
                psum[j] += d;
            }
            *(float4*)(node_out + (size_t)n * C + 4 * tx) = o;
        }
    }

    #pragma unroll
    for (int j = 0; j < 4; j++) atomicAdd(&s_red[4 * tx + j], psum[j]);
    __syncthreads();

    // ---- per-block partials ----
    if (tid < C) g_part[blockIdx.x][tid] = s_red[tid];
    if (tid == C) {
        float ms = 0.f;
        #pragma unroll 8
        for (int i = 0; i < TILE_N; i++) ms += s_mask[i];
        g_part[blockIdx.x][C] = ms;
    }
    __threadfence();
    __syncthreads();

    if (tid == 0) s_last = (atomicAdd(&g_count, 1) == (int)gridDim.x - 1);
    __syncthreads();

    // ---- last block reduces all partials ----
    if (s_last) {
        int nb = gridDim.x;
        if (tid < C) {
            float s = 0.f;
            for (int b = 0; b < nb; b++) s += g_part[b][tid];
            s_red[tid] = s;
        } else if (tid == C) {
            float ms = 0.f;
            for (int b = 0; b < nb; b++) ms += g_part[b][C];
            s_msum = ms;
        }
        __syncthreads();
        if (tid < C) out[tid] = s_red[tid] / s_msum;
        if (tid == 0) g_count = 0;   // reset for next graph replay
    }
}

extern "C" void kernel_launch(void* const* d_in, const int* in_sizes, int n_in,
                              void* d_out, int out_size) {
    const float* node_repr = (const float*)d_in[0];
    const float* maskp     = (const float*)d_in[1];
    const float* cent      = (const float*)d_in[2];
    float* out = (float*)d_out;

    int N = in_sizes[1];   // mask element count == node count
    int blocks = (N + TILE_N - 1) / TILE_N;
    if (blocks > MAXB) blocks = MAXB;

    int smem_bytes = (2 * E * STRIDE + 6 * 64) * (int)sizeof(float);
    cudaFuncSetAttribute(cd_kernel, cudaFuncAttributeMaxDynamicSharedMemorySize, smem_bytes);

    cd_kernel<<<blocks, THREADS, smem_bytes>>>(node_repr, maskp, cent, out, N);
}